// round 6
// baseline (speedup 1.0000x reference)
#include <cuda_runtime.h>
#include <cuda.h>
#include <cstdint>

// ---------------------------------------------------------------------------
// Block-sparse attention prefill (HSA), TMA-pipelined, register-retiled.
// Per (l, h): for each of S=16 selected 64x128 KV blocks:
//   scores = q . K_blk * sm_scale ; p = softmax_64(scores) * w * valid
//   o += p . V_blk
// B=1, Lq=256, Lkv=4096, HQ=32, H=2, D=128, S=16, BS=64, G=16.
// QK: lane = (d-half, key-quad) -> 4 keys x 4 heads per lane.
// PV: lane = (u-half, d-octet)  -> 8 d x 4 heads per lane.
// ---------------------------------------------------------------------------

#define FMA2(acc, a, b) asm("fma.rn.f32x2 %0, %1, %2, %0;" : "+l"(acc) : "l"(a), "l"(b))

__device__ __forceinline__ void unpack2(unsigned long long v, float& lo, float& hi) {
    asm("mov.b64 {%0, %1}, %2;" : "=f"(lo), "=f"(hi) : "l"(v));
}
__device__ __forceinline__ unsigned long long dup2(float f) {
    unsigned long long r;
    asm("mov.b64 %0, {%1, %1};" : "=l"(r) : "f"(f));
    return r;
}
__device__ __forceinline__ uint32_t su32(const void* p) {
    return (uint32_t)__cvta_generic_to_shared(p);
}

#define MBAR_INIT(a, c) \
    asm volatile("mbarrier.init.shared.b64 [%0], %1;" :: "r"(a), "r"(c) : "memory")
#define MBAR_EXPECT(a, b) \
    asm volatile("mbarrier.arrive.expect_tx.shared.b64 _, [%0], %1;" :: "r"(a), "r"(b) : "memory")
#define TMA3D(smem, map, x, y, z, mbar) \
    asm volatile("cp.async.bulk.tensor.3d.shared::cta.global.tile.mbarrier::complete_tx::bytes " \
                 "[%0], [%1, {%2, %3, %4}], [%5];" \
                 :: "r"(smem), "l"(map), "r"(x), "r"(y), "r"(z), "r"(mbar) : "memory")

__device__ __forceinline__ void mbar_wait(uint32_t mbar, uint32_t parity) {
    asm volatile(
        "{\n\t.reg .pred P;\n"
        "LW_%=:\n\t"
        "mbarrier.try_wait.parity.acquire.cta.shared::cta.b64 P, [%0], %1, 0x989680;\n\t"
        "@P bra LD_%=;\n\t"
        "bra LW_%=;\n"
        "LD_%=:\n\t}" :: "r"(mbar), "r"(parity) : "memory");
}

namespace hsa {
constexpr int LQ = 256, HQn = 32, Hn = 2, Dn = 128, Sn = 16, BSn = 64, Gn = 16;
constexpr float SM_SCALE = 0.08838834764831845f;  // 1/sqrt(128)

constexpr int TILE_B = 32768;            // 64 rows x 512B = 4 SW128 panels of 8KB
constexpr int KB0    = 0;
constexpr int KB1    = 32768;
constexpr int VB     = 65536;
constexpr int QS_OFF = 98304;            // 2048 f32 (16 heads x 128, pre-scaled)
constexpr int PS_OFF = 106496;           // 4 warps x 64 u x 16B (p[u][g] float4)
constexpr int WS_OFF = 110592;           // 256 f32
constexpr int BI_OFF = 111616;           // 16 int
constexpr int MB_OFF = 111680;           // 3 mbarriers
constexpr int SMEM_BYTES = 111744;       // x2 CTAs <= 228KB/SM
}  // namespace hsa
using namespace hsa;

template <bool USE_TMA>
__global__ __launch_bounds__(128, 2)
void hsa_prefill(const __grid_constant__ CUtensorMap tmk,
                 const __grid_constant__ CUtensorMap tmv,
                 const float* __restrict__ q, const float* __restrict__ k,
                 const float* __restrict__ v, const float* __restrict__ w,
                 const int* __restrict__ bi, float* __restrict__ out)
{
    extern __shared__ char sm[];
    float* qs  = (float*)(sm + QS_OFF);
    float* wsm = (float*)(sm + WS_OFF);
    int*   bis = (int*)(sm + BI_OFF);
    const uint32_t mb = su32(sm + MB_OFF);   // +0: kbar0, +8: kbar1, +16: vbar

    const int h    = blockIdx.x;
    const int l    = blockIdx.y;
    const int tid  = threadIdx.x;
    const int warp = tid >> 5;
    const int lane = tid & 31;

    if (USE_TMA && tid == 0) {
        MBAR_INIT(mb + 0, 1);
        MBAR_INIT(mb + 8, 1);
        MBAR_INIT(mb + 16, 1);
    }

    // --- Stage q (pre-scaled), w, block indices ---
    {
        const float4* qg = (const float4*)(q + (size_t)(l * HQn + h * Gn) * Dn);
        float4* qs4 = (float4*)qs;
        #pragma unroll
        for (int j = 0; j < 4; ++j) {
            int i = tid + j * 128;
            float4 t = qg[i];
            t.x *= SM_SCALE; t.y *= SM_SCALE; t.z *= SM_SCALE; t.w *= SM_SCALE;
            qs4[i] = t;
        }
        if (tid < 64)
            ((float4*)wsm)[tid] =
                ((const float4*)(w + (size_t)(l * HQn + h * Gn) * Sn))[tid];
        if (tid < 16)
            bis[tid] = bi[(l * Hn + h) * Sn + tid];
    }
    __syncthreads();

    // --- Prologue: launch K_0 ---
    if (USE_TMA && tid == 0) {
        int b0 = max(bis[0], 0) * BSn;
        MBAR_EXPECT(mb + 0, TILE_B);
        #pragma unroll
        for (int p = 0; p < 4; ++p)
            TMA3D(su32(sm + KB0 + p * 8192), &tmk, 32 * p, h, b0, mb + 0);
    }

    const int g0 = warp * 4;                 // 4 query heads per warp
    const int kq = lane & 15;                // key-quad (QK) / d-octet (PV)
    const int dh = lane >> 4;                // d-half (QK) / u-half (PV)
    float* psw = (float*)(sm + PS_OFF + warp * 1024);   // p[u][g] float4 per warp

    // QK per-lane constants: 4 key rows
    int urow[4], u7x[4];
    #pragma unroll
    for (int j = 0; j < 4; ++j) {
        int u = kq * 4 + j;
        urow[j] = u * 128;
        u7x[j]  = (u & 7) << 4;
    }
    // PV per-lane constants: 2 d-chunks (16B each) of the lane's 8 dims
    const int vc0 = (kq * 2) & 7;            // in-panel chunk
    const char* vpanel = sm + VB + (kq >> 2) * 8192;

    unsigned long long o[4][4];              // o[g][dpair-pair]: 4 f32x2 = 8 d each g
    #pragma unroll
    for (int a = 0; a < 4; ++a)
        #pragma unroll
        for (int b = 0; b < 4; ++b) o[a][b] = 0ull;

    uint32_t kph0 = 0, kph1 = 0, vph = 0;
    const float4* kb4 = (const float4*)(k + h * Dn);
    const float4* vb4 = (const float4*)(v + h * Dn);

    for (int s = 0; s < Sn; ++s) {
        const int blkraw = bis[s];
        const int blkc   = max(blkraw, 0);

        __syncthreads();   // prev iter's smem readers done (V buf + other K buf free)

        const char* kt;
        if (USE_TMA) {
            if (tid == 0) {
                MBAR_EXPECT(mb + 16, TILE_B);
                #pragma unroll
                for (int p = 0; p < 4; ++p)
                    TMA3D(su32(sm + VB + p * 8192), &tmv, 32 * p, h, blkc * BSn, mb + 16);
                if (s + 1 < Sn) {
                    int bn = max(bis[s + 1], 0) * BSn;
                    uint32_t kbar = mb + 8u * ((s + 1) & 1);
                    char* kdst = sm + (((s + 1) & 1) ? KB1 : KB0);
                    MBAR_EXPECT(kbar, TILE_B);
                    #pragma unroll
                    for (int p = 0; p < 4; ++p)
                        TMA3D(su32(kdst + p * 8192), &tmk, 32 * p, h, bn, kbar);
                }
            }
            if (s & 1) { mbar_wait(mb + 8, kph1); kph1 ^= 1; }
            else       { mbar_wait(mb + 0, kph0); kph0 ^= 1; }
            kt = sm + ((s & 1) ? KB1 : KB0);
        } else {
            const float4* krow = kb4 + (size_t)blkc * BSn * 64;
            const float4* vrow = vb4 + (size_t)blkc * BSn * 64;
            #pragma unroll
            for (int j = 0; j < 16; ++j) {
                int c = tid + j * 128;
                int u = c >> 5, d4 = c & 31;
                int panel = d4 >> 3, chunk = d4 & 7;
                int so = panel * 8192 + u * 128 + ((chunk ^ (u & 7)) << 4);
                *(float4*)(sm + KB0 + so) = krow[u * 64 + d4];
                *(float4*)(sm + VB  + so) = vrow[u * 64 + d4];
            }
            __syncthreads();
            kt = sm + KB0;
        }

        // --- QK: lane owns 4 keys x 4 heads over its 64-dim half ---
        unsigned long long acc[4][4];        // [g][key j]
        #pragma unroll
        for (int a = 0; a < 4; ++a)
            #pragma unroll
            for (int b = 0; b < 4; ++b) acc[a][b] = 0ull;

        #pragma unroll
        for (int cc = 0; cc < 16; ++cc) {
            const char* kpan = kt + (dh * 2 + (cc >> 3)) * 8192;
            const int cof = (cc & 7) << 4;
            ulonglong2 kv[4];
            #pragma unroll
            for (int j = 0; j < 4; ++j)
                kv[j] = *(const ulonglong2*)(kpan + urow[j] + (cof ^ u7x[j]));
            const float* qd = qs + dh * 64 + cc * 4;
            #pragma unroll
            for (int g = 0; g < 4; ++g) {
                ulonglong2 qv = *(const ulonglong2*)(qd + (g0 + g) * Dn);
                #pragma unroll
                for (int j = 0; j < 4; ++j) {
                    FMA2(acc[g][j], qv.x, kv[j].x);
                    FMA2(acc[g][j], qv.y, kv[j].y);
                }
            }
        }

        // --- softmax over 64 keys (per head): combine d-halves, butterfly over kq ---
        float p_[4][4];
        #pragma unroll
        for (int g = 0; g < 4; ++g) {
            float sc[4];
            #pragma unroll
            for (int j = 0; j < 4; ++j) {
                float x, y;
                unpack2(acc[g][j], x, y);
                sc[j] = x + y;
                sc[j] += __shfl_xor_sync(0xffffffffu, sc[j], 16);   // d-half combine
            }
            float m = fmaxf(fmaxf(sc[0], sc[1]), fmaxf(sc[2], sc[3]));
            #pragma unroll
            for (int off = 8; off > 0; off >>= 1)
                m = fmaxf(m, __shfl_xor_sync(0xffffffffu, m, off));
            float e0 = __expf(sc[0] - m), e1 = __expf(sc[1] - m);
            float e2 = __expf(sc[2] - m), e3 = __expf(sc[3] - m);
            float sum = (e0 + e1) + (e2 + e3);
            #pragma unroll
            for (int off = 8; off > 0; off >>= 1)
                sum += __shfl_xor_sync(0xffffffffu, sum, off);
            float wv = (blkraw >= 0) ? wsm[(g0 + g) * Sn + s] : 0.0f;
            float coef = __fdividef(wv, sum);
            p_[g][0] = e0 * coef; p_[g][1] = e1 * coef;
            p_[g][2] = e2 * coef; p_[g][3] = e3 * coef;
        }
        if (dh == 0) {
            #pragma unroll
            for (int j = 0; j < 4; ++j)
                *(float4*)(psw + (kq * 4 + j) * 4) =
                    make_float4(p_[0][j], p_[1][j], p_[2][j], p_[3][j]);
        }
        __syncwarp();

        // --- wait V_s (hidden behind QK+softmax) ---
        if (USE_TMA) { mbar_wait(mb + 16, vph); vph ^= 1; }

        // --- PV: lane owns 8 d x 4 heads over its 32-key half ---
        #pragma unroll 8
        for (int ul = 0; ul < 32; ++ul) {
            const int u = dh * 32 + ul;
            float4 pv4 = *(const float4*)(psw + u * 4);          // p[u][g0..g0+3]
            const int sw = (u & 7) << 4;
            const char* vrow = vpanel + u * 128;
            ulonglong2 va = *(const ulonglong2*)(vrow + ((vc0 << 4) ^ sw));
            ulonglong2 vb = *(const ulonglong2*)(vrow + (((vc0 + 1) << 4) ^ sw));
            unsigned long long pk0 = dup2(pv4.x), pk1 = dup2(pv4.y);
            unsigned long long pk2 = dup2(pv4.z), pk3 = dup2(pv4.w);
            FMA2(o[0][0], pk0, va.x); FMA2(o[0][1], pk0, va.y);
            FMA2(o[0][2], pk0, vb.x); FMA2(o[0][3], pk0, vb.y);
            FMA2(o[1][0], pk1, va.x); FMA2(o[1][1], pk1, va.y);
            FMA2(o[1][2], pk1, vb.x); FMA2(o[1][3], pk1, vb.y);
            FMA2(o[2][0], pk2, va.x); FMA2(o[2][1], pk2, va.y);
            FMA2(o[2][2], pk2, vb.x); FMA2(o[2][3], pk2, vb.y);
            FMA2(o[3][0], pk3, va.x); FMA2(o[3][1], pk3, va.y);
            FMA2(o[3][2], pk3, vb.x); FMA2(o[3][3], pk3, vb.y);
        }
    }

    // --- combine u-halves of o, then write out[l, h*16+g, kq*8 .. +7] ---
    float* op = out + (size_t)(l * HQn + h * Gn) * Dn + kq * 8;
    #pragma unroll
    for (int g = 0; g < 4; ++g) {
        float f[8];
        #pragma unroll
        for (int c = 0; c < 4; ++c) {
            float lo, hi;
            unpack2(o[g][c], lo, hi);
            lo += __shfl_xor_sync(0xffffffffu, lo, 16);
            hi += __shfl_xor_sync(0xffffffffu, hi, 16);
            f[c * 2] = lo; f[c * 2 + 1] = hi;
        }
        if (dh == 0) {
            *(float4*)(op + (g0 + g) * Dn)     = make_float4(f[0], f[1], f[2], f[3]);
            *(float4*)(op + (g0 + g) * Dn + 4) = make_float4(f[4], f[5], f[6], f[7]);
        }
    }
}

// ---------------------------------------------------------------------------
// Host
// ---------------------------------------------------------------------------

typedef CUresult (*EncodeTiled_t)(
    CUtensorMap*, CUtensorMapDataType, cuuint32_t, void*,
    const cuuint64_t*, const cuuint64_t*, const cuuint32_t*, const cuuint32_t*,
    CUtensorMapInterleave, CUtensorMapSwizzle, CUtensorMapL2promotion,
    CUtensorMapFloatOOBfill);

static EncodeTiled_t get_encode_fn() {
    void* fn = nullptr;
    cudaDriverEntryPointQueryResult qr = cudaDriverEntryPointSymbolNotFound;
#if CUDART_VERSION >= 12050
    if (cudaGetDriverEntryPointByVersion("cuTensorMapEncodeTiled", &fn, 12000,
                                         cudaEnableDefault, &qr) != cudaSuccess ||
        qr != cudaDriverEntryPointSuccess)
        fn = nullptr;
#else
    if (cudaGetDriverEntryPoint("cuTensorMapEncodeTiled", &fn,
                                cudaEnableDefault, &qr) != cudaSuccess ||
        qr != cudaDriverEntryPointSuccess)
        fn = nullptr;
#endif
    return (EncodeTiled_t)fn;
}

static bool make_map(EncodeTiled_t enc, CUtensorMap* tm, const void* base) {
    cuuint64_t dims[3]    = {128, 2, 4096};
    cuuint64_t strides[2] = {128ull * 4ull, 256ull * 4ull};
    cuuint32_t box[3]     = {32, 1, 64};
    cuuint32_t estr[3]    = {1, 1, 1};
    CUresult r = enc(tm, CU_TENSOR_MAP_DATA_TYPE_FLOAT32, 3, (void*)base,
                     dims, strides, box, estr,
                     CU_TENSOR_MAP_INTERLEAVE_NONE, CU_TENSOR_MAP_SWIZZLE_128B,
                     CU_TENSOR_MAP_L2_PROMOTION_L2_128B,
                     CU_TENSOR_MAP_FLOAT_OOB_FILL_NONE);
    return r == CUDA_SUCCESS;
}

extern "C" void kernel_launch(void* const* d_in, const int* in_sizes, int n_in,
                              void* d_out, int out_size) {
    const float* q  = (const float*)d_in[0];
    const float* k  = (const float*)d_in[1];
    const float* v  = (const float*)d_in[2];
    const float* w  = (const float*)d_in[3];
    const int*   bi = (const int*)d_in[4];
    float* out = (float*)d_out;

    CUtensorMap tmk, tmv;
    __builtin_memset(&tmk, 0, sizeof(tmk));
    __builtin_memset(&tmv, 0, sizeof(tmv));

    EncodeTiled_t enc = get_encode_fn();
    bool tma_ok = enc && make_map(enc, &tmk, k) && make_map(enc, &tmv, v);

    dim3 grid(Hn, LQ);
    if (tma_ok) {
        cudaFuncSetAttribute(hsa_prefill<true>,
                             cudaFuncAttributeMaxDynamicSharedMemorySize, SMEM_BYTES);
        hsa_prefill<true><<<grid, 128, SMEM_BYTES>>>(tmk, tmv, q, k, v, w, bi, out);
    } else {
        cudaFuncSetAttribute(hsa_prefill<false>,
                             cudaFuncAttributeMaxDynamicSharedMemorySize, SMEM_BYTES);
        hsa_prefill<false><<<grid, 128, SMEM_BYTES>>>(tmk, tmv, q, k, v, w, bi, out);
    }
}

// round 7
// speedup vs baseline: 1.2249x; 1.2249x over previous
#include <cuda_runtime.h>
#include <cuda.h>
#include <cstdint>

// ---------------------------------------------------------------------------
// Block-sparse attention prefill (HSA), TMA-pipelined + PV/QK software fusion.
// Per (l, h): for each of S=16 selected 64x128 KV blocks:
//   scores = q . K_blk * sm_scale ; p = softmax_64(scores) * w * valid
//   o += p . V_blk
// B=1, Lq=256, Lkv=4096, HQ=32, H=2, D=128, S=16, BS=64, G=16.
// Body(s): QK(s) PhaseA | wait V(s-1) | PhaseB = QK(s) tail + PV(s-1) fused.
// ---------------------------------------------------------------------------

#define FMA2(acc, a, b) asm("fma.rn.f32x2 %0, %1, %2, %0;" : "+l"(acc) : "l"(a), "l"(b))

__device__ __forceinline__ void unpack2(unsigned long long v, float& lo, float& hi) {
    asm("mov.b64 {%0, %1}, %2;" : "=f"(lo), "=f"(hi) : "l"(v));
}
__device__ __forceinline__ unsigned long long pack2(float lo, float hi) {
    unsigned long long r;
    asm("mov.b64 %0, {%1, %2};" : "=l"(r) : "f"(lo), "f"(hi));
    return r;
}
__device__ __forceinline__ uint32_t su32(const void* p) {
    return (uint32_t)__cvta_generic_to_shared(p);
}

#define MBAR_INIT(a, c) \
    asm volatile("mbarrier.init.shared.b64 [%0], %1;" :: "r"(a), "r"(c) : "memory")
#define MBAR_EXPECT(a, b) \
    asm volatile("mbarrier.arrive.expect_tx.shared.b64 _, [%0], %1;" :: "r"(a), "r"(b) : "memory")
#define TMA3D(smem, map, x, y, z, mbar) \
    asm volatile("cp.async.bulk.tensor.3d.shared::cta.global.tile.mbarrier::complete_tx::bytes " \
                 "[%0], [%1, {%2, %3, %4}], [%5];" \
                 :: "r"(smem), "l"(map), "r"(x), "r"(y), "r"(z), "r"(mbar) : "memory")

__device__ __forceinline__ void mbar_wait(uint32_t mbar, uint32_t parity) {
    asm volatile(
        "{\n\t.reg .pred P;\n"
        "LW_%=:\n\t"
        "mbarrier.try_wait.parity.acquire.cta.shared::cta.b64 P, [%0], %1, 0x989680;\n\t"
        "@P bra LD_%=;\n\t"
        "bra LW_%=;\n"
        "LD_%=:\n\t}" :: "r"(mbar), "r"(parity) : "memory");
}

namespace hsa {
constexpr int LQ = 256, HQn = 32, Hn = 2, Dn = 128, Sn = 16, BSn = 64, Gn = 16;
constexpr float SM_SCALE = 0.08838834764831845f;  // 1/sqrt(128)

constexpr int TILE_B = 32768;            // 64 rows x 512B = 4 SW128 panels of 8KB
constexpr int KB0    = 0;
constexpr int KB1    = 32768;
constexpr int VB     = 65536;
constexpr int QS_OFF = 98304;            // 2048 f32 (16 heads x 128, pre-scaled)
constexpr int PS_OFF = 106496;           // 4 warps x 64 u x 8 f32 (p dup {p,p})
constexpr int WS_OFF = 114688;           // 256 f32
constexpr int BI_OFF = 115712;           // 16 int
constexpr int MB_OFF = 115776;           // 3 mbarriers
constexpr int SMEM_BYTES = 115840;       // x2 CTAs <= 228KB/SM
}  // namespace hsa
using namespace hsa;

template <bool USE_TMA>
__global__ __launch_bounds__(128, 2)
void hsa_prefill(const __grid_constant__ CUtensorMap tmk,
                 const __grid_constant__ CUtensorMap tmv,
                 const float* __restrict__ q, const float* __restrict__ k,
                 const float* __restrict__ v, const float* __restrict__ w,
                 const int* __restrict__ bi, float* __restrict__ out)
{
    extern __shared__ char sm[];
    float* qs  = (float*)(sm + QS_OFF);
    float* wsm = (float*)(sm + WS_OFF);
    int*   bis = (int*)(sm + BI_OFF);
    const uint32_t mb = su32(sm + MB_OFF);   // +0: kbar0, +8: kbar1, +16: vbar

    const int h    = blockIdx.x;
    const int l    = blockIdx.y;
    const int tid  = threadIdx.x;
    const int warp = tid >> 5;
    const int lane = tid & 31;

    if (USE_TMA && tid == 0) {
        MBAR_INIT(mb + 0, 1);
        MBAR_INIT(mb + 8, 1);
        MBAR_INIT(mb + 16, 1);
    }

    // --- Stage q (pre-scaled), w, block indices ---
    {
        const float4* qg = (const float4*)(q + (size_t)(l * HQn + h * Gn) * Dn);
        float4* qs4 = (float4*)qs;
        #pragma unroll
        for (int j = 0; j < 4; ++j) {
            int i = tid + j * 128;
            float4 t = qg[i];
            t.x *= SM_SCALE; t.y *= SM_SCALE; t.z *= SM_SCALE; t.w *= SM_SCALE;
            qs4[i] = t;
        }
        if (tid < 64)
            ((float4*)wsm)[tid] =
                ((const float4*)(w + (size_t)(l * HQn + h * Gn) * Sn))[tid];
        if (tid < 16)
            bis[tid] = bi[(l * Hn + h) * Sn + tid];
    }
    __syncthreads();

    const int g0  = warp * 4;                // 4 query heads per warp
    const int lx8 = (lane & 7) << 4;         // SW128 per-lane xor (bytes)
    float* psw = (float*)(sm + PS_OFF) + warp * 512;

    unsigned long long o[4][2];
    #pragma unroll
    for (int a = 0; a < 4; ++a) { o[a][0] = 0ull; o[a][1] = 0ull; }

    unsigned long long acc[4][2];
    const char* kt = sm + KB0;
    const char* vt = sm + VB + (lane >> 3) * 8192;   // lane's 32-float d-panel

    // One QK chunk: 2 K-loads + 4 q-loads -> 16 FMA2 (conflict-free, R4 pattern)
    auto qk_chunk = [&](int p4, int cc) {
        const char* kp0 = kt + p4 * 8192 + lane * 128;
        const char* kp1 = kp0 + 4096;        // +32 rows; (lane+32)&7 == lane&7
        int co = (cc << 4) ^ lx8;
        ulonglong2 ka = *(const ulonglong2*)(kp0 + co);
        ulonglong2 kc = *(const ulonglong2*)(kp1 + co);
        const float* qd = qs + p4 * 32 + cc * 4;
        #pragma unroll
        for (int gj = 0; gj < 4; ++gj) {
            ulonglong2 qv = *(const ulonglong2*)(qd + (g0 + gj) * Dn);
            FMA2(acc[gj][0], qv.x, ka.x);
            FMA2(acc[gj][0], qv.y, ka.y);
            FMA2(acc[gj][1], qv.x, kc.x);
            FMA2(acc[gj][1], qv.y, kc.y);
        }
    };
    // One PV step (key u): 3 LDS -> 8 FMA2 (conflict-free, R4 pattern)
    auto pv_u = [&](int u) {
        ulonglong2 pa = *(const ulonglong2*)(psw + u * 8);      // {p0,p0},{p1,p1}
        ulonglong2 pb = *(const ulonglong2*)(psw + u * 8 + 4);  // {p2,p2},{p3,p3}
        ulonglong2 vv = *(const ulonglong2*)(vt + u * 128 + (lx8 ^ ((u & 7) << 4)));
        FMA2(o[0][0], pa.x, vv.x); FMA2(o[0][1], pa.x, vv.y);
        FMA2(o[1][0], pa.y, vv.x); FMA2(o[1][1], pa.y, vv.y);
        FMA2(o[2][0], pb.x, vv.x); FMA2(o[2][1], pb.x, vv.y);
        FMA2(o[3][0], pb.y, vv.x); FMA2(o[3][1], pb.y, vv.y);
    };
    // softmax over 64 keys + weight coef; store p duplicated {p,p}
    auto softmax_store = [&](int s, int blkraw) {
        #pragma unroll
        for (int gj = 0; gj < 4; ++gj) {
            float a0, a1, b0, b1;
            unpack2(acc[gj][0], a0, a1);
            unpack2(acc[gj][1], b0, b1);
            float s0 = a0 + a1;
            float s1 = b0 + b1;
            float m = fmaxf(s0, s1);
            #pragma unroll
            for (int off = 16; off > 0; off >>= 1)
                m = fmaxf(m, __shfl_xor_sync(0xffffffffu, m, off));
            float e0 = __expf(s0 - m);
            float e1 = __expf(s1 - m);
            float sum = e0 + e1;
            #pragma unroll
            for (int off = 16; off > 0; off >>= 1)
                sum += __shfl_xor_sync(0xffffffffu, sum, off);
            float wv = (blkraw >= 0) ? wsm[(g0 + gj) * Sn + s] : 0.0f;
            float coef = __fdividef(wv, sum);
            e0 *= coef; e1 *= coef;
            *(unsigned long long*)(psw + lane * 8 + gj * 2)        = pack2(e0, e0);
            *(unsigned long long*)(psw + (lane + 32) * 8 + gj * 2) = pack2(e1, e1);
        }
        __syncwarp();
    };

    if constexpr (USE_TMA) {
        uint32_t kph0 = 0, kph1 = 0, vph = 0;

        // --- Prologue: K(0), K(1), V(0) all in flight ---
        if (tid == 0) {
            int b0 = max(bis[0], 0) * BSn;
            int b1 = max(bis[1], 0) * BSn;
            MBAR_EXPECT(mb + 0, TILE_B);
            #pragma unroll
            for (int p = 0; p < 4; ++p)
                TMA3D(su32(sm + KB0 + p * 8192), &tmk, 32 * p, h, b0, mb + 0);
            MBAR_EXPECT(mb + 8, TILE_B);
            #pragma unroll
            for (int p = 0; p < 4; ++p)
                TMA3D(su32(sm + KB1 + p * 8192), &tmk, 32 * p, h, b1, mb + 8);
            MBAR_EXPECT(mb + 16, TILE_B);
            #pragma unroll
            for (int p = 0; p < 4; ++p)
                TMA3D(su32(sm + VB + p * 8192), &tmv, 32 * p, h, b0, mb + 16);
        }

        // --- Body s=0 (no PV yet) ---
        mbar_wait(mb + 0, kph0); kph0 ^= 1;
        kt = sm + KB0;
        #pragma unroll
        for (int a = 0; a < 4; ++a) { acc[a][0] = 0ull; acc[a][1] = 0ull; }
        #pragma unroll 8
        for (int i = 0; i < 32; ++i) qk_chunk(i >> 3, i & 7);
        __syncthreads();                       // all warps done with KB0 reads
        softmax_store(0, bis[0]);

        // --- Bodies s = 1..15: fused PV(s-1) + QK(s) ---
        for (int s = 1; s < Sn; ++s) {
            const int blkraw = bis[s];
            if (tid == 0 && s + 1 < Sn) {      // K(s+1): full-body hiding window
                int bn = max(bis[s + 1], 0) * BSn;
                uint32_t kbar = mb + 8u * ((s + 1) & 1);
                char* kdst = sm + (((s + 1) & 1) ? KB1 : KB0);
                MBAR_EXPECT(kbar, TILE_B);
                #pragma unroll
                for (int p = 0; p < 4; ++p)
                    TMA3D(su32(kdst + p * 8192), &tmk, 32 * p, h, bn, kbar);
            }
            if (s & 1) { mbar_wait(mb + 8, kph1); kph1 ^= 1; }
            else       { mbar_wait(mb + 0, kph0); kph0 ^= 1; }
            kt = sm + ((s & 1) ? KB1 : KB0);

            #pragma unroll
            for (int a = 0; a < 4; ++a) { acc[a][0] = 0ull; acc[a][1] = 0ull; }

            // Phase A: first half of QK(s)
            #pragma unroll 8
            for (int i = 0; i < 16; ++i) qk_chunk(i >> 3, i & 7);

            // V(s-1) arrival (issued end of body s-1 / prologue)
            mbar_wait(mb + 16, vph); vph ^= 1;

            // Phase B: QK(s) tail fused with PV(s-1) — two independent streams
            #pragma unroll 4
            for (int i = 0; i < 16; ++i) {
                qk_chunk(2 + (i >> 3), i & 7);
                pv_u(4 * i);
                pv_u(4 * i + 1);
                pv_u(4 * i + 2);
                pv_u(4 * i + 3);
            }

            __syncthreads();                   // PhaseB readers of vbuf + kbuf done
            if (tid == 0) {                    // V(s) into the (now free) vbuf
                int bv = max(blkraw, 0) * BSn;
                MBAR_EXPECT(mb + 16, TILE_B);
                #pragma unroll
                for (int p = 0; p < 4; ++p)
                    TMA3D(su32(sm + VB + p * 8192), &tmv, 32 * p, h, bv, mb + 16);
            }
            softmax_store(s, blkraw);
        }

        // --- Epilogue: PV(15) ---
        mbar_wait(mb + 16, vph); vph ^= 1;
        #pragma unroll 8
        for (int u = 0; u < BSn; ++u) pv_u(u);
    } else {
        // Fallback: unfused gather path (R4-proven)
        const float4* kb4 = (const float4*)(k + h * Dn);
        const float4* vb4 = (const float4*)(v + h * Dn);
        for (int s = 0; s < Sn; ++s) {
            const int blkraw = bis[s];
            const int blkc   = max(blkraw, 0);
            __syncthreads();
            const float4* krow = kb4 + (size_t)blkc * BSn * 64;
            const float4* vrow = vb4 + (size_t)blkc * BSn * 64;
            #pragma unroll
            for (int j = 0; j < 16; ++j) {
                int c = tid + j * 128;
                int u = c >> 5, d4 = c & 31;
                int panel = d4 >> 3, chunk = d4 & 7;
                int so = panel * 8192 + u * 128 + ((chunk ^ (u & 7)) << 4);
                *(float4*)(sm + KB0 + so) = krow[u * 64 + d4];
                *(float4*)(sm + VB  + so) = vrow[u * 64 + d4];
            }
            __syncthreads();
            kt = sm + KB0;
            #pragma unroll
            for (int a = 0; a < 4; ++a) { acc[a][0] = 0ull; acc[a][1] = 0ull; }
            #pragma unroll 8
            for (int i = 0; i < 32; ++i) qk_chunk(i >> 3, i & 7);
            softmax_store(s, blkraw);
            #pragma unroll 8
            for (int u = 0; u < BSn; ++u) pv_u(u);
        }
    }

    // --- write O: lane covers d = lane*4 .. +3 (matches PV panel mapping) ---
    float* op = out + (size_t)(l * HQn + h * Gn) * Dn;
    #pragma unroll
    for (int gj = 0; gj < 4; ++gj) {
        float f0, f1, f2, f3;
        unpack2(o[gj][0], f0, f1);
        unpack2(o[gj][1], f2, f3);
        *(float4*)(op + (g0 + gj) * Dn + lane * 4) = make_float4(f0, f1, f2, f3);
    }
}

// ---------------------------------------------------------------------------
// Host
// ---------------------------------------------------------------------------

typedef CUresult (*EncodeTiled_t)(
    CUtensorMap*, CUtensorMapDataType, cuuint32_t, void*,
    const cuuint64_t*, const cuuint64_t*, const cuuint32_t*, const cuuint32_t*,
    CUtensorMapInterleave, CUtensorMapSwizzle, CUtensorMapL2promotion,
    CUtensorMapFloatOOBfill);

static EncodeTiled_t get_encode_fn() {
    void* fn = nullptr;
    cudaDriverEntryPointQueryResult qr = cudaDriverEntryPointSymbolNotFound;
#if CUDART_VERSION >= 12050
    if (cudaGetDriverEntryPointByVersion("cuTensorMapEncodeTiled", &fn, 12000,
                                         cudaEnableDefault, &qr) != cudaSuccess ||
        qr != cudaDriverEntryPointSuccess)
        fn = nullptr;
#else
    if (cudaGetDriverEntryPoint("cuTensorMapEncodeTiled", &fn,
                                cudaEnableDefault, &qr) != cudaSuccess ||
        qr != cudaDriverEntryPointSuccess)
        fn = nullptr;
#endif
    return (EncodeTiled_t)fn;
}

static bool make_map(EncodeTiled_t enc, CUtensorMap* tm, const void* base) {
    cuuint64_t dims[3]    = {128, 2, 4096};
    cuuint64_t strides[2] = {128ull * 4ull, 256ull * 4ull};
    cuuint32_t box[3]     = {32, 1, 64};
    cuuint32_t estr[3]    = {1, 1, 1};
    CUresult r = enc(tm, CU_TENSOR_MAP_DATA_TYPE_FLOAT32, 3, (void*)base,
                     dims, strides, box, estr,
                     CU_TENSOR_MAP_INTERLEAVE_NONE, CU_TENSOR_MAP_SWIZZLE_128B,
                     CU_TENSOR_MAP_L2_PROMOTION_L2_128B,
                     CU_TENSOR_MAP_FLOAT_OOB_FILL_NONE);
    return r == CUDA_SUCCESS;
}

extern "C" void kernel_launch(void* const* d_in, const int* in_sizes, int n_in,
                              void* d_out, int out_size) {
    const float* q  = (const float*)d_in[0];
    const float* k  = (const float*)d_in[1];
    const float* v  = (const float*)d_in[2];
    const float* w  = (const float*)d_in[3];
    const int*   bi = (const int*)d_in[4];
    float* out = (float*)d_out;

    CUtensorMap tmk, tmv;
    __builtin_memset(&tmk, 0, sizeof(tmk));
    __builtin_memset(&tmv, 0, sizeof(tmv));

    EncodeTiled_t enc = get_encode_fn();
    bool tma_ok = enc && make_map(enc, &tmk, k) && make_map(enc, &tmv, v);

    dim3 grid(Hn, LQ);
    if (tma_ok) {
        cudaFuncSetAttribute(hsa_prefill<true>,
                             cudaFuncAttributeMaxDynamicSharedMemorySize, SMEM_BYTES);
        hsa_prefill<true><<<grid, 128, SMEM_BYTES>>>(tmk, tmv, q, k, v, w, bi, out);
    } else {
        cudaFuncSetAttribute(hsa_prefill<false>,
                             cudaFuncAttributeMaxDynamicSharedMemorySize, SMEM_BYTES);
        hsa_prefill<false><<<grid, 128, SMEM_BYTES>>>(tmk, tmv, q, k, v, w, bi, out);
    }
}

// round 9
// speedup vs baseline: 4.1809x; 3.4132x over previous
#include <cuda_runtime.h>
#include <cuda.h>
#include <cstdint>

// ---------------------------------------------------------------------------
// Block-sparse attention prefill (HSA) on tensor cores (mma.sync m16n8k8 tf32).
// Per (l, h): for each of S=16 selected 64x128 KV blocks:
//   scores = q . K_blk * sm_scale ; p = softmax_64(scores) * w * valid
//   o += p . V_blk
// B=1, Lq=256, Lkv=4096, HQ=32, H=2, D=128, S=16, BS=64, G=16.
// QK: M=16(g) N=64(u) K=128(d), warps split u (16 each), q A-frags in regs.
// PV: M=16(g) N=128(d) K=64(u), warps split d (32 each), P via smem.
// K/V via TMA SW128 (K double-buffered, V single) — R4-proven pipeline.
// ---------------------------------------------------------------------------

__device__ __forceinline__ uint32_t su32(const void* p) {
    return (uint32_t)__cvta_generic_to_shared(p);
}
__device__ __forceinline__ uint32_t tf32cvt(float f) {
    uint32_t r;
    asm("cvt.rna.tf32.f32 %0, %1;" : "=r"(r) : "f"(f));
    return r;
}
__device__ __forceinline__ void mma_tf32(float* c, const uint32_t* a,
                                         uint32_t b0, uint32_t b1) {
    asm volatile(
        "mma.sync.aligned.m16n8k8.row.col.f32.tf32.tf32.f32 "
        "{%0,%1,%2,%3}, {%4,%5,%6,%7}, {%8,%9}, {%0,%1,%2,%3};"
        : "+f"(c[0]), "+f"(c[1]), "+f"(c[2]), "+f"(c[3])
        : "r"(a[0]), "r"(a[1]), "r"(a[2]), "r"(a[3]), "r"(b0), "r"(b1));
}

#define MBAR_INIT(a, c) \
    asm volatile("mbarrier.init.shared.b64 [%0], %1;" :: "r"(a), "r"(c) : "memory")
#define MBAR_EXPECT(a, b) \
    asm volatile("mbarrier.arrive.expect_tx.shared.b64 _, [%0], %1;" :: "r"(a), "r"(b) : "memory")
#define TMA3D(smem, map, x, y, z, mbar) \
    asm volatile("cp.async.bulk.tensor.3d.shared::cta.global.tile.mbarrier::complete_tx::bytes " \
                 "[%0], [%1, {%2, %3, %4}], [%5];" \
                 :: "r"(smem), "l"(map), "r"(x), "r"(y), "r"(z), "r"(mbar) : "memory")

__device__ __forceinline__ void mbar_wait(uint32_t mbar, uint32_t parity) {
    asm volatile(
        "{\n\t.reg .pred P;\n"
        "LW_%=:\n\t"
        "mbarrier.try_wait.parity.acquire.cta.shared::cta.b64 P, [%0], %1, 0x989680;\n\t"
        "@P bra LD_%=;\n\t"
        "bra LW_%=;\n"
        "LD_%=:\n\t}" :: "r"(mbar), "r"(parity) : "memory");
}

namespace hsa {
constexpr int LQ = 256, HQn = 32, Hn = 2, Dn = 128, Sn = 16, BSn = 64, Gn = 16;
constexpr float SM_SCALE = 0.08838834764831845f;  // 1/sqrt(128)

constexpr int TILE_B = 32768;            // 64 rows x 512B = 4 SW128 panels of 8KB
constexpr int KB0    = 0;
constexpr int KB1    = 32768;
constexpr int VB     = 65536;
constexpr int PSTR   = 68;               // P row stride (floats)
constexpr int P_OFF  = 98304;            // 16 x 68 f32 = 4352 B
constexpr int EX_OFF = 102656;           // 16 rows x 4 warps x float2 = 512 B
constexpr int WS_OFF = 103168;           // 256 f32 = 1024 B
constexpr int BI_OFF = 104192;           // 16 int
constexpr int MB_OFF = 104256;           // 3 mbarriers
constexpr int SMEM_BYTES = 104320;       // x2 CTAs = 208640 <= 228KB/SM
}  // namespace hsa
using namespace hsa;

template <bool USE_TMA>
__global__ __launch_bounds__(128, 2)
void hsa_mma(const __grid_constant__ CUtensorMap tmk,
             const __grid_constant__ CUtensorMap tmv,
             const float* __restrict__ q, const float* __restrict__ k,
             const float* __restrict__ v, const float* __restrict__ w,
             const int* __restrict__ bi, float* __restrict__ out)
{
    extern __shared__ char sm[];
    float*  Pb  = (float*)(sm + P_OFF);
    float2* ex  = (float2*)(sm + EX_OFF);
    float*  wsm = (float*)(sm + WS_OFF);
    int*    bis = (int*)(sm + BI_OFF);
    const uint32_t mb = su32(sm + MB_OFF);   // +0: kbar0, +8: kbar1, +16: vbar

    const int h    = blockIdx.x;
    const int l    = blockIdx.y;
    const int tid  = threadIdx.x;
    const int warp = tid >> 5;
    const int lane = tid & 31;
    const int gid  = lane >> 2;      // 0..7
    const int t4   = lane & 3;       // 0..3

    if (USE_TMA && tid == 0) {
        MBAR_INIT(mb + 0, 1);
        MBAR_INIT(mb + 8, 1);
        MBAR_INIT(mb + 16, 1);
    }
    // stage w, block indices
    if (tid < 64)
        ((float4*)wsm)[tid] = ((const float4*)(w + (size_t)(l * HQn + h * Gn) * Sn))[tid];
    if (tid < 16)
        bis[tid] = bi[(l * Hn + h) * Sn + tid];
    __syncthreads();

    // --- q A-fragments, tf32, pre-scaled: qa[ks] covers d = 8ks..8ks+7 ---
    uint32_t qa[16][4];
    {
        const float* qb = q + (size_t)(l * HQn + h * Gn) * Dn;
        #pragma unroll
        for (int ks = 0; ks < 16; ++ks) {
            int d0 = 8 * ks;
            qa[ks][0] = tf32cvt(qb[gid * Dn + d0 + t4] * SM_SCALE);
            qa[ks][1] = tf32cvt(qb[(gid + 8) * Dn + d0 + t4] * SM_SCALE);
            qa[ks][2] = tf32cvt(qb[gid * Dn + d0 + t4 + 4] * SM_SCALE);
            qa[ks][3] = tf32cvt(qb[(gid + 8) * Dn + d0 + t4 + 4] * SM_SCALE);
        }
    }

    // --- prologue: K(0) ---
    if (USE_TMA && tid == 0) {
        int b0 = max(bis[0], 0) * BSn;
        MBAR_EXPECT(mb + 0, TILE_B);
        #pragma unroll
        for (int p = 0; p < 4; ++p)
            TMA3D(su32(sm + KB0 + p * 8192), &tmk, 32 * p, h, b0, mb + 0);
    }

    float oc[4][4];                      // PV accum: 4 n-tiles (d=32w..+31) x 4
    #pragma unroll
    for (int a = 0; a < 4; ++a)
        #pragma unroll
        for (int b = 0; b < 4; ++b) oc[a][b] = 0.0f;

    const int rowa = (16 * warp + gid) * 128;       // QK: K row bases (bytes)
    const int rowb = rowa + 8 * 128;
    const char* vtile = sm + VB + warp * 8192;      // PV: warp's d-panel
    const int r0 = gid, r1 = gid + 8;               // C-fragment rows (g)

    uint32_t kph0 = 0, kph1 = 0, vph = 0;
    const float4* kb4 = (const float4*)(k + h * Dn);
    const float4* vb4 = (const float4*)(v + h * Dn);

    for (int s = 0; s < Sn; ++s) {
        const int blkraw = bis[s];
        const int blkc   = max(blkraw, 0);

        __syncthreads();   // prev iter readers done (V buf + other K buf free)

        const char* kt;
        if constexpr (USE_TMA) {
            if (tid == 0) {
                MBAR_EXPECT(mb + 16, TILE_B);
                #pragma unroll
                for (int p = 0; p < 4; ++p)
                    TMA3D(su32(sm + VB + p * 8192), &tmv, 32 * p, h, blkc * BSn, mb + 16);
                if (s + 1 < Sn) {
                    int bn = max(bis[s + 1], 0) * BSn;
                    uint32_t kbar = mb + 8u * ((s + 1) & 1);
                    char* kdst = sm + (((s + 1) & 1) ? KB1 : KB0);
                    MBAR_EXPECT(kbar, TILE_B);
                    #pragma unroll
                    for (int p = 0; p < 4; ++p)
                        TMA3D(su32(kdst + p * 8192), &tmk, 32 * p, h, bn, kbar);
                }
            }
            if (s & 1) { mbar_wait(mb + 8, kph1); kph1 ^= 1; }
            else       { mbar_wait(mb + 0, kph0); kph0 ^= 1; }
            kt = sm + ((s & 1) ? KB1 : KB0);
        } else {
            // fallback gather: LDG -> SW128-swizzled STS
            const float4* krow = kb4 + (size_t)blkc * BSn * 64;
            const float4* vrow = vb4 + (size_t)blkc * BSn * 64;
            #pragma unroll
            for (int j = 0; j < 16; ++j) {
                int c = tid + j * 128;
                int u = c >> 5, d4 = c & 31;
                int panel = d4 >> 3, chunk = d4 & 7;
                int so = panel * 8192 + u * 128 + ((chunk ^ (u & 7)) << 4);
                *(float4*)(sm + KB0 + so) = krow[u * 64 + d4];
                *(float4*)(sm + VB  + so) = vrow[u * 64 + d4];
            }
            __syncthreads();
            kt = sm + KB0;
        }

        // --- QK: warp's 16 keys (u = 16w..16w+15), 2 n-tiles x 16 k-steps ---
        float c0[4] = {0.f, 0.f, 0.f, 0.f};   // n-tile 0: u = 16w + 0..7
        float c1[4] = {0.f, 0.f, 0.f, 0.f};   // n-tile 1: u = 16w + 8..15
        #pragma unroll
        for (int ks = 0; ks < 16; ++ks) {
            const char* bp = kt + (ks >> 2) * 8192;
            const int cA = ((2 * ks) & 7) ^ gid;       // swizzled chunk, b0
            const int cB = ((2 * ks + 1) & 7) ^ gid;   // b1
            uint32_t b0a = *(const uint32_t*)(bp + rowa + (cA << 4) + t4 * 4);
            uint32_t b1a = *(const uint32_t*)(bp + rowa + (cB << 4) + t4 * 4);
            uint32_t b0b = *(const uint32_t*)(bp + rowb + (cA << 4) + t4 * 4);
            uint32_t b1b = *(const uint32_t*)(bp + rowb + (cB << 4) + t4 * 4);
            mma_tf32(c0, qa[ks], b0a, b1a);
            mma_tf32(c1, qa[ks], b0b, b1b);
        }

        // --- softmax over 64 u (cross-warp via one smem exchange) ---
        // rows: r0 holds c*[0],c*[1]; r1 holds c*[2],c*[3]
        float m0 = fmaxf(fmaxf(c0[0], c0[1]), fmaxf(c1[0], c1[1]));
        float m1 = fmaxf(fmaxf(c0[2], c0[3]), fmaxf(c1[2], c1[3]));
        m0 = fmaxf(m0, __shfl_xor_sync(0xffffffffu, m0, 1));
        m0 = fmaxf(m0, __shfl_xor_sync(0xffffffffu, m0, 2));
        m1 = fmaxf(m1, __shfl_xor_sync(0xffffffffu, m1, 1));
        m1 = fmaxf(m1, __shfl_xor_sync(0xffffffffu, m1, 2));
        float e00 = __expf(c0[0] - m0), e01 = __expf(c0[1] - m0);
        float e10 = __expf(c1[0] - m0), e11 = __expf(c1[1] - m0);
        float f00 = __expf(c0[2] - m1), f01 = __expf(c0[3] - m1);
        float f10 = __expf(c1[2] - m1), f11 = __expf(c1[3] - m1);
        float S0 = (e00 + e01) + (e10 + e11);
        float S1 = (f00 + f01) + (f10 + f11);
        S0 += __shfl_xor_sync(0xffffffffu, S0, 1);
        S0 += __shfl_xor_sync(0xffffffffu, S0, 2);
        S1 += __shfl_xor_sync(0xffffffffu, S1, 1);
        S1 += __shfl_xor_sync(0xffffffffu, S1, 2);
        if (t4 == 0) {
            ex[r0 * 4 + warp] = make_float2(m0, S0);
            ex[r1 * 4 + warp] = make_float2(m1, S1);
        }
        __syncthreads();
        float4 xa0 = *(const float4*)(ex + r0 * 4);
        float4 xb0 = *(const float4*)(ex + r0 * 4 + 2);
        float4 xa1 = *(const float4*)(ex + r1 * 4);
        float4 xb1 = *(const float4*)(ex + r1 * 4 + 2);
        float M0 = fmaxf(fmaxf(xa0.x, xa0.z), fmaxf(xb0.x, xb0.z));
        float M1 = fmaxf(fmaxf(xa1.x, xa1.z), fmaxf(xb1.x, xb1.z));
        float G0 = xa0.y * __expf(xa0.x - M0) + xa0.w * __expf(xa0.z - M0)
                 + xb0.y * __expf(xb0.x - M0) + xb0.w * __expf(xb0.z - M0);
        float G1 = xa1.y * __expf(xa1.x - M1) + xa1.w * __expf(xa1.z - M1)
                 + xb1.y * __expf(xb1.x - M1) + xb1.w * __expf(xb1.z - M1);
        float wv0 = (blkraw >= 0) ? wsm[r0 * Sn + s] : 0.0f;
        float wv1 = (blkraw >= 0) ? wsm[r1 * Sn + s] : 0.0f;
        float sc0 = __fdividef(__expf(m0 - M0) * wv0, G0);
        float sc1 = __fdividef(__expf(m1 - M1) * wv1, G1);

        // --- store P (tf32 bits) : cols u = 16w + 8t + 2*t4 + {0,1} ---
        {
            int cbase = 16 * warp + 2 * t4;
            unsigned long long v0 =
                ((unsigned long long)tf32cvt(e01 * sc0) << 32) | tf32cvt(e00 * sc0);
            unsigned long long v1 =
                ((unsigned long long)tf32cvt(e11 * sc0) << 32) | tf32cvt(e10 * sc0);
            unsigned long long v2 =
                ((unsigned long long)tf32cvt(f01 * sc1) << 32) | tf32cvt(f00 * sc1);
            unsigned long long v3 =
                ((unsigned long long)tf32cvt(f11 * sc1) << 32) | tf32cvt(f10 * sc1);
            *(unsigned long long*)(Pb + r0 * PSTR + cbase)     = v0;
            *(unsigned long long*)(Pb + r0 * PSTR + cbase + 8) = v1;
            *(unsigned long long*)(Pb + r1 * PSTR + cbase)     = v2;
            *(unsigned long long*)(Pb + r1 * PSTR + cbase + 8) = v3;
        }

        if constexpr (USE_TMA) { mbar_wait(mb + 16, vph); vph ^= 1; }
        __syncthreads();       // P visible to all warps; V tile resident

        // --- PV: warp's 32 dims (d = 32w..+31), 4 n-tiles x 8 k-steps ---
        // k-permutation: mma k = t4 <-> u0+2*t4 ; k = t4+4 <-> u0+2*t4+1
        #pragma unroll
        for (int ku = 0; ku < 8; ++ku) {
            int u0 = 8 * ku;
            float2 a02 = *(const float2*)(Pb + gid * PSTR + u0 + 2 * t4);
            float2 a13 = *(const float2*)(Pb + (gid + 8) * PSTR + u0 + 2 * t4);
            uint32_t A[4] = {__float_as_uint(a02.x), __float_as_uint(a13.x),
                             __float_as_uint(a02.y), __float_as_uint(a13.y)};
            int ua = u0 + 2 * t4;
            int ub = ua + 1;
            int raV = ua * 128 + (gid & 3) * 4;
            int rbV = ub * 128 + (gid & 3) * 4;
            int ua7 = ua & 7, ub7 = ub & 7;
            #pragma unroll
            for (int nt = 0; nt < 4; ++nt) {
                int ch = (2 * nt + (gid >> 2)) & 7;
                uint32_t b0 = *(const uint32_t*)(vtile + raV + ((ch ^ ua7) << 4));
                uint32_t b1 = *(const uint32_t*)(vtile + rbV + ((ch ^ ub7) << 4));
                mma_tf32(oc[nt], A, b0, b1);
            }
        }
    }

    // --- write O: warp's d-slice; C rows r0/r1, cols d = 32w + 8nt + 2t4 + {0,1}
    float* op = out + (size_t)(l * HQn + h * Gn) * Dn;
    #pragma unroll
    for (int nt = 0; nt < 4; ++nt) {
        int d = 32 * warp + 8 * nt + 2 * t4;
        *(float2*)(op + r0 * Dn + d) = make_float2(oc[nt][0], oc[nt][1]);
        *(float2*)(op + r1 * Dn + d) = make_float2(oc[nt][2], oc[nt][3]);
    }
}

// ---------------------------------------------------------------------------
// Host
// ---------------------------------------------------------------------------

typedef CUresult (*EncodeTiled_t)(
    CUtensorMap*, CUtensorMapDataType, cuuint32_t, void*,
    const cuuint64_t*, const cuuint64_t*, const cuuint32_t*, const cuuint32_t*,
    CUtensorMapInterleave, CUtensorMapSwizzle, CUtensorMapL2promotion,
    CUtensorMapFloatOOBfill);

static EncodeTiled_t get_encode_fn() {
    void* fn = nullptr;
    cudaDriverEntryPointQueryResult qr = cudaDriverEntryPointSymbolNotFound;
#if CUDART_VERSION >= 12050
    if (cudaGetDriverEntryPointByVersion("cuTensorMapEncodeTiled", &fn, 12000,
                                         cudaEnableDefault, &qr) != cudaSuccess ||
        qr != cudaDriverEntryPointSuccess)
        fn = nullptr;
#else
    if (cudaGetDriverEntryPoint("cuTensorMapEncodeTiled", &fn,
                                cudaEnableDefault, &qr) != cudaSuccess ||
        qr != cudaDriverEntryPointSuccess)
        fn = nullptr;
#endif
    return (EncodeTiled_t)fn;
}

static bool make_map(EncodeTiled_t enc, CUtensorMap* tm, const void* base) {
    cuuint64_t dims[3]    = {128, 2, 4096};
    cuuint64_t strides[2] = {128ull * 4ull, 256ull * 4ull};
    cuuint32_t box[3]     = {32, 1, 64};
    cuuint32_t estr[3]    = {1, 1, 1};
    CUresult r = enc(tm, CU_TENSOR_MAP_DATA_TYPE_FLOAT32, 3, (void*)base,
                     dims, strides, box, estr,
                     CU_TENSOR_MAP_INTERLEAVE_NONE, CU_TENSOR_MAP_SWIZZLE_128B,
                     CU_TENSOR_MAP_L2_PROMOTION_L2_128B,
                     CU_TENSOR_MAP_FLOAT_OOB_FILL_NONE);
    return r == CUDA_SUCCESS;
}

extern "C" void kernel_launch(void* const* d_in, const int* in_sizes, int n_in,
                              void* d_out, int out_size) {
    const float* q  = (const float*)d_in[0];
    const float* k  = (const float*)d_in[1];
    const float* v  = (const float*)d_in[2];
    const float* w  = (const float*)d_in[3];
    const int*   bi = (const int*)d_in[4];
    float* out = (float*)d_out;

    CUtensorMap tmk, tmv;
    __builtin_memset(&tmk, 0, sizeof(tmk));
    __builtin_memset(&tmv, 0, sizeof(tmv));

    EncodeTiled_t enc = get_encode_fn();
    bool tma_ok = enc && make_map(enc, &tmk, k) && make_map(enc, &tmv, v);

    dim3 grid(Hn, LQ);
    if (tma_ok) {
        cudaFuncSetAttribute(hsa_mma<true>,
                             cudaFuncAttributeMaxDynamicSharedMemorySize, SMEM_BYTES);
        hsa_mma<true><<<grid, 128, SMEM_BYTES>>>(tmk, tmv, q, k, v, w, bi, out);
    } else {
        cudaFuncSetAttribute(hsa_mma<false>,
                             cudaFuncAttributeMaxDynamicSharedMemorySize, SMEM_BYTES);
        hsa_mma<false><<<grid, 128, SMEM_BYTES>>>(tmk, tmv, q, k, v, w, bi, out);
    }
}